// round 4
// baseline (speedup 1.0000x reference)
#include <cuda_runtime.h>
#include <math.h>

// ---------------------------------------------------------------------------
// Problem constants
// ---------------------------------------------------------------------------
#define BATCH   32
#define L_SER   32768
#define PATCH   32          // PS
#define DMODEL  256         // D
#define T_TOK   1024        // L / PS
#define QKV_N   768         // 3*D
#define ROWS    (BATCH * T_TOK)   // 32768 token rows

// ---------------------------------------------------------------------------
// Device scratch (static: no allocation allowed)
// ---------------------------------------------------------------------------
__device__ float  g_patches[BATCH * L_SER];                 // x_norm == patches, 4 MB
__device__ float  g_qkv[(size_t)ROWS * QKV_N];              // 96 MB
__device__ float  g_attnout[(size_t)ROWS * DMODEL];         // 32 MB  (attn@V, pre-proj)
__device__ float  g_Weff[PATCH * QKV_N];                    // W_proj @ W_qkv   [32,768]
__device__ float  g_beff[QKV_N];                            // b_proj@W_qkv + b_qkv
__device__ float  g_Wph[DMODEL * PATCH];                    // W_out @ W_head   [256,32]
__device__ float  g_bph[PATCH];                             // b_out@W_head + b_head
__device__ double g_loss_acc;

// ---------------------------------------------------------------------------
// K1: fold weights + zero loss accumulator
//   Weff[k][j]  = sum_d Wproj[k][d] * Wqkv[d][j]          (k<32, j<768)
//   beff[j]     = sum_d bproj[d]    * Wqkv[d][j] + bqkv[j]
//   Wph[d][p]   = sum_e Wout[d][e]  * Whead[e][p]          (d<256, p<32)
//   bph[p]      = sum_e bout[e]     * Whead[e][p] + bhead[p]
// ---------------------------------------------------------------------------
__global__ void prep_kernel(const float* __restrict__ Wproj, const float* __restrict__ bproj,
                            const float* __restrict__ Wqkv,  const float* __restrict__ bqkv,
                            const float* __restrict__ Wout,  const float* __restrict__ bout,
                            const float* __restrict__ Whead, const float* __restrict__ bhead)
{
    int idx = blockIdx.x * blockDim.x + threadIdx.x;
    if (idx == 0) g_loss_acc = 0.0;

    if (idx < PATCH * QKV_N) {                       // 24576: Weff
        int k = idx / QKV_N, j = idx % QKV_N;
        float acc = 0.f;
        #pragma unroll 8
        for (int d = 0; d < DMODEL; d++)
            acc = fmaf(Wproj[k * DMODEL + d], Wqkv[d * QKV_N + j], acc);
        g_Weff[idx] = acc;
    } else if (idx < PATCH * QKV_N + QKV_N) {        // 768: beff
        int j = idx - PATCH * QKV_N;
        float acc = bqkv[j];
        #pragma unroll 8
        for (int d = 0; d < DMODEL; d++)
            acc = fmaf(bproj[d], Wqkv[d * QKV_N + j], acc);
        g_beff[j] = acc;
    } else if (idx < PATCH * QKV_N + QKV_N + DMODEL * PATCH) {   // 8192: Wph
        int t = idx - (PATCH * QKV_N + QKV_N);
        int d = t / PATCH, p = t % PATCH;
        float acc = 0.f;
        #pragma unroll 8
        for (int e = 0; e < DMODEL; e++)
            acc = fmaf(Wout[d * DMODEL + e], Whead[e * PATCH + p], acc);
        g_Wph[t] = acc;
    } else if (idx < PATCH * QKV_N + QKV_N + DMODEL * PATCH + PATCH) {  // 32: bph
        int p = idx - (PATCH * QKV_N + QKV_N + DMODEL * PATCH);
        float acc = bhead[p];
        #pragma unroll 8
        for (int e = 0; e < DMODEL; e++)
            acc = fmaf(bout[e], Whead[e * PATCH + p], acc);
        g_bph[p] = acc;
    }
}

// ---------------------------------------------------------------------------
// K2: instance norm over full series per batch row (ddof=1, +1e-5 on std)
// ---------------------------------------------------------------------------
__global__ void instnorm_kernel(const float* __restrict__ x)
{
    int b   = blockIdx.x;
    int tid = threadIdx.x;                 // 256 threads
    const float* xr = x + (size_t)b * L_SER;
    float*       pr = g_patches + (size_t)b * L_SER;

    float s = 0.f, ss = 0.f;
    for (int i = tid * 4; i < L_SER; i += 256 * 4) {
        float4 v = *(const float4*)(xr + i);
        s  += v.x + v.y + v.z + v.w;
        ss += v.x * v.x + v.y * v.y + v.z * v.z + v.w * v.w;
    }
    // warp reduce
    #pragma unroll
    for (int w = 16; w >= 1; w >>= 1) {
        s  += __shfl_xor_sync(0xffffffffu, s,  w);
        ss += __shfl_xor_sync(0xffffffffu, ss, w);
    }
    __shared__ float rs[8], rss[8];
    __shared__ float sh_mean, sh_inv;
    int lane = tid & 31, warp = tid >> 5;
    if (lane == 0) { rs[warp] = s; rss[warp] = ss; }
    __syncthreads();
    if (tid == 0) {
        float ts = 0.f, tss = 0.f;
        #pragma unroll
        for (int w = 0; w < 8; w++) { ts += rs[w]; tss += rss[w]; }
        float mean = ts / (float)L_SER;
        float var  = (tss - (float)L_SER * mean * mean) / (float)(L_SER - 1);
        float std  = sqrtf(var) + 1e-5f;
        sh_mean = mean;
        sh_inv  = 1.0f / std;
    }
    __syncthreads();
    float mean = sh_mean, inv = sh_inv;
    for (int i = tid * 4; i < L_SER; i += 256 * 4) {
        float4 v = *(const float4*)(xr + i);
        v.x = (v.x - mean) * inv; v.y = (v.y - mean) * inv;
        v.z = (v.z - mean) * inv; v.w = (v.w - mean) * inv;
        *(float4*)(pr + i) = v;
    }
}

// ---------------------------------------------------------------------------
// K3: qkv = patches[32768,32] @ Weff[32,768] + beff   -> g_qkv [32768,768]
//   CTA tile 64x64, 256 threads, 4x4 per thread, K=32 in one shot.
// ---------------------------------------------------------------------------
__global__ __launch_bounds__(256) void qkv_gemm_kernel()
{
    __shared__ __align__(16) float Ap[64][33];
    __shared__ __align__(16) float Bp[32][68];

    int tid = threadIdx.x;
    int ty  = tid >> 4, tx = tid & 15;       // 16x16
    int row0 = blockIdx.y * 64;
    int col0 = blockIdx.x * 64;

    for (int i = tid; i < 64 * 32; i += 256) {
        int r = i >> 5, k = i & 31;
        Ap[r][k] = g_patches[(size_t)(row0 + r) * PATCH + k];
    }
    for (int i = tid; i < 32 * 64; i += 256) {
        int k = i >> 6, c = i & 63;
        Bp[k][c] = g_Weff[k * QKV_N + col0 + c];
    }
    __syncthreads();

    float acc[4][4];
    #pragma unroll
    for (int i = 0; i < 4; i++)
        #pragma unroll
        for (int j = 0; j < 4; j++) acc[i][j] = 0.f;

    #pragma unroll
    for (int k = 0; k < 32; k++) {
        float a[4];
        #pragma unroll
        for (int i = 0; i < 4; i++) a[i] = Ap[ty * 4 + i][k];
        float4 b4 = *(const float4*)&Bp[k][tx * 4];
        #pragma unroll
        for (int i = 0; i < 4; i++) {
            acc[i][0] = fmaf(a[i], b4.x, acc[i][0]);
            acc[i][1] = fmaf(a[i], b4.y, acc[i][1]);
            acc[i][2] = fmaf(a[i], b4.z, acc[i][2]);
            acc[i][3] = fmaf(a[i], b4.w, acc[i][3]);
        }
    }

    float4 bias = *(const float4*)&g_beff[col0 + tx * 4];
    #pragma unroll
    for (int i = 0; i < 4; i++) {
        float4 o;
        o.x = acc[i][0] + bias.x; o.y = acc[i][1] + bias.y;
        o.z = acc[i][2] + bias.z; o.w = acc[i][3] + bias.w;
        *(float4*)(g_qkv + (size_t)(row0 + ty * 4 + i) * QKV_N + col0 + tx * 4) = o;
    }
}

// ---------------------------------------------------------------------------
// K4: causal flash attention (fp32). Grid (16, 32) = (qblock, batch).
//   BM=BN=64, D=256. Q resident in SMEM; K/V streamed in 64x64 chunks.
//   Per thread (16x16 layout): S tile 4x4, O tile 4 rows x 4 chunks x float4.
// ---------------------------------------------------------------------------
#define KS_STRIDE 68
#define ATTN_SMEM (64*256*4 + 3*(64*KS_STRIDE*4))   // 117760 bytes

__global__ __launch_bounds__(256, 1) void attention_kernel()
{
    extern __shared__ __align__(16) float smem[];
    float* Qs = smem;                       // [64][256]
    float* Ks = Qs + 64 * 256;              // [64][68]
    float* Ps = Ks + 64 * KS_STRIDE;        // [64][68]
    float* Vs = Ps + 64 * KS_STRIDE;        // [64][68]

    int tid = threadIdx.x;
    int ty  = tid >> 4, tx = tid & 15;
    int ty4 = ty * 4,  tx4 = tx * 4;
    int qb  = 15 - blockIdx.x;              // heavy blocks launch first
    int b   = blockIdx.y;

    const float* qbase = g_qkv + ((size_t)b * T_TOK + qb * 64) * QKV_N;       // q offset 0

    // load Q block: 64 rows x 256 cols
    for (int i = tid; i < 64 * 64; i += 256) {          // 4096 float4
        int r = i >> 6, c4 = i & 63;
        *(float4*)&Qs[r * 256 + c4 * 4] = *(const float4*)(qbase + (size_t)r * QKV_N + c4 * 4);
    }
    __syncthreads();

    float m[4], l[4];
    float4 O[4][4];
    #pragma unroll
    for (int i = 0; i < 4; i++) {
        m[i] = -1e30f; l[i] = 0.f;
        #pragma unroll
        for (int dc = 0; dc < 4; dc++) O[i][dc] = make_float4(0.f, 0.f, 0.f, 0.f);
    }

    for (int j = 0; j <= qb; j++) {
        const float* kbase = g_qkv + ((size_t)b * T_TOK + j * 64) * QKV_N + DMODEL;      // k
        const float* vbase = g_qkv + ((size_t)b * T_TOK + j * 64) * QKV_N + 2 * DMODEL;  // v

        // ---- S = Q @ K^T over D in 4 chunks of 64 ----
        float S[4][4];
        #pragma unroll
        for (int i = 0; i < 4; i++)
            #pragma unroll
            for (int jj = 0; jj < 4; jj++) S[i][jj] = 0.f;

        for (int dc = 0; dc < 4; dc++) {
            __syncthreads();
            for (int i = tid; i < 64 * 16; i += 256) {   // 1024 float4
                int r = i >> 4, c4 = i & 15;
                *(float4*)&Ks[r * KS_STRIDE + c4 * 4] =
                    *(const float4*)(kbase + (size_t)r * QKV_N + dc * 64 + c4 * 4);
            }
            __syncthreads();
            #pragma unroll
            for (int d = 0; d < 64; d += 4) {
                float4 qv[4], kv[4];
                #pragma unroll
                for (int i = 0; i < 4; i++) qv[i] = *(const float4*)&Qs[(ty4 + i) * 256 + dc * 64 + d];
                #pragma unroll
                for (int i = 0; i < 4; i++) kv[i] = *(const float4*)&Ks[(tx4 + i) * KS_STRIDE + d];
                #pragma unroll
                for (int i = 0; i < 4; i++)
                    #pragma unroll
                    for (int jj = 0; jj < 4; jj++) {
                        S[i][jj] = fmaf(qv[i].x, kv[jj].x, S[i][jj]);
                        S[i][jj] = fmaf(qv[i].y, kv[jj].y, S[i][jj]);
                        S[i][jj] = fmaf(qv[i].z, kv[jj].z, S[i][jj]);
                        S[i][jj] = fmaf(qv[i].w, kv[jj].w, S[i][jj]);
                    }
            }
        }

        // ---- scale, causal mask, online softmax ----
        bool diag = (j == qb);
        #pragma unroll
        for (int i = 0; i < 4; i++) {
            float mx = -1e30f;
            #pragma unroll
            for (int jj = 0; jj < 4; jj++) {
                float s = S[i][jj] * 0.0625f;                    // 1/sqrt(256)
                if (diag && (tx4 + jj) > (ty4 + i)) s = -1e30f;  // same block offset
                S[i][jj] = s;
                mx = fmaxf(mx, s);
            }
            #pragma unroll
            for (int w = 8; w >= 1; w >>= 1)
                mx = fmaxf(mx, __shfl_xor_sync(0xffffffffu, mx, w));
            float mnew  = fmaxf(m[i], mx);
            float alpha = __expf(m[i] - mnew);
            float ls = 0.f;
            #pragma unroll
            for (int jj = 0; jj < 4; jj++) {
                float p = __expf(S[i][jj] - mnew);
                Ps[(ty4 + i) * KS_STRIDE + tx4 + jj] = p;
                ls += p;
            }
            #pragma unroll
            for (int w = 8; w >= 1; w >>= 1)
                ls += __shfl_xor_sync(0xffffffffu, ls, w);
            l[i] = l[i] * alpha + ls;
            m[i] = mnew;
            #pragma unroll
            for (int dc = 0; dc < 4; dc++) {
                O[i][dc].x *= alpha; O[i][dc].y *= alpha;
                O[i][dc].z *= alpha; O[i][dc].w *= alpha;
            }
        }

        // ---- O += P @ V over D in 4 chunks of 64 ----
        for (int dc = 0; dc < 4; dc++) {
            __syncthreads();   // Ps written (dc=0) / previous Vs consumed
            for (int i = tid; i < 64 * 16; i += 256) {
                int r = i >> 4, c4 = i & 15;
                *(float4*)&Vs[r * KS_STRIDE + c4 * 4] =
                    *(const float4*)(vbase + (size_t)r * QKV_N + dc * 64 + c4 * 4);
            }
            __syncthreads();
            #pragma unroll
            for (int s = 0; s < 64; s += 4) {
                float4 pv[4], vv[4];
                #pragma unroll
                for (int i = 0; i < 4; i++)  pv[i] = *(const float4*)&Ps[(ty4 + i) * KS_STRIDE + s];
                #pragma unroll
                for (int ss = 0; ss < 4; ss++) vv[ss] = *(const float4*)&Vs[(s + ss) * KS_STRIDE + tx4];
                #pragma unroll
                for (int i = 0; i < 4; i++) {
                    O[i][dc].x = fmaf(pv[i].x, vv[0].x, O[i][dc].x);
                    O[i][dc].x = fmaf(pv[i].y, vv[1].x, O[i][dc].x);
                    O[i][dc].x = fmaf(pv[i].z, vv[2].x, O[i][dc].x);
                    O[i][dc].x = fmaf(pv[i].w, vv[3].x, O[i][dc].x);
                    O[i][dc].y = fmaf(pv[i].x, vv[0].y, O[i][dc].y);
                    O[i][dc].y = fmaf(pv[i].y, vv[1].y, O[i][dc].y);
                    O[i][dc].y = fmaf(pv[i].z, vv[2].y, O[i][dc].y);
                    O[i][dc].y = fmaf(pv[i].w, vv[3].y, O[i][dc].y);
                    O[i][dc].z = fmaf(pv[i].x, vv[0].z, O[i][dc].z);
                    O[i][dc].z = fmaf(pv[i].y, vv[1].z, O[i][dc].z);
                    O[i][dc].z = fmaf(pv[i].z, vv[2].z, O[i][dc].z);
                    O[i][dc].z = fmaf(pv[i].w, vv[3].z, O[i][dc].z);
                    O[i][dc].w = fmaf(pv[i].x, vv[0].w, O[i][dc].w);
                    O[i][dc].w = fmaf(pv[i].y, vv[1].w, O[i][dc].w);
                    O[i][dc].w = fmaf(pv[i].z, vv[2].w, O[i][dc].w);
                    O[i][dc].w = fmaf(pv[i].w, vv[3].w, O[i][dc].w);
                }
            }
        }
    }

    // ---- normalize + store ----
    #pragma unroll
    for (int i = 0; i < 4; i++) {
        float inv = 1.0f / l[i];
        #pragma unroll
        for (int dc = 0; dc < 4; dc++) {
            float4 o = O[i][dc];
            o.x *= inv; o.y *= inv; o.z *= inv; o.w *= inv;
            *(float4*)(g_attnout + ((size_t)b * T_TOK + qb * 64 + ty4 + i) * DMODEL + dc * 64 + tx4) = o;
        }
    }
}

// ---------------------------------------------------------------------------
// K5: pred = attnout @ Wph + bph, fused next-patch MSE accumulation.
//   One warp per row (lane = patch element). 256 CTAs x 8 warps, grid-stride.
// ---------------------------------------------------------------------------
__global__ __launch_bounds__(256) void pred_loss_kernel()
{
    __shared__ float Ws[DMODEL * PATCH];    // 32 KB
    int tid = threadIdx.x;
    for (int i = tid; i < DMODEL * PATCH; i += 256) Ws[i] = g_Wph[i];
    __syncthreads();

    int lane = tid & 31, warp = tid >> 5;
    int gw = blockIdx.x * 8 + warp;
    int nw = gridDim.x * 8;
    float bias = g_bph[lane];

    float lsum = 0.f;
    for (int row = gw; row < ROWS; row += nw) {
        const float* orow = g_attnout + (size_t)row * DMODEL;
        float acc = bias;
        #pragma unroll
        for (int kb = 0; kb < 8; kb++) {
            float ov = orow[kb * 32 + lane];
            #pragma unroll
            for (int k2 = 0; k2 < 32; k2++) {
                float o = __shfl_sync(0xffffffffu, ov, k2);
                acc = fmaf(o, Ws[(kb * 32 + k2) * 32 + lane], acc);
            }
        }
        if ((row & (T_TOK - 1)) != T_TOK - 1) {          // t < 1023
            float d = acc - g_patches[(size_t)(row + 1) * PATCH + lane];
            lsum = fmaf(d, d, lsum);
        }
    }
    #pragma unroll
    for (int w = 16; w >= 1; w >>= 1)
        lsum += __shfl_xor_sync(0xffffffffu, lsum, w);
    if (lane == 0) atomicAdd(&g_loss_acc, (double)lsum);
}

// ---------------------------------------------------------------------------
// K6: finalize
// ---------------------------------------------------------------------------
__global__ void finalize_kernel(float* out)
{
    // denominator: B * (T-1) * PS = 32 * 1023 * 32
    out[0] = (float)(g_loss_acc / (double)(BATCH * (T_TOK - 1) * PATCH));
}

// ---------------------------------------------------------------------------
// Launch
// ---------------------------------------------------------------------------
extern "C" void kernel_launch(void* const* d_in, const int* in_sizes, int n_in,
                              void* d_out, int out_size)
{
    const float* x      = (const float*)d_in[0];
    const float* Wproj  = (const float*)d_in[1];
    const float* bproj  = (const float*)d_in[2];
    const float* Wqkv   = (const float*)d_in[3];
    const float* bqkv   = (const float*)d_in[4];
    const float* Wout   = (const float*)d_in[5];
    const float* bout   = (const float*)d_in[6];
    const float* Whead  = (const float*)d_in[7];
    const float* bhead  = (const float*)d_in[8];
    float* out = (float*)d_out;

    cudaFuncSetAttribute(attention_kernel,
                         cudaFuncAttributeMaxDynamicSharedMemorySize, ATTN_SMEM);

    // K1: weight folding + zero accumulator (33568 outputs)
    prep_kernel<<<132, 256>>>(Wproj, bproj, Wqkv, bqkv, Wout, bout, Whead, bhead);

    // K2: instance norm, one CTA per batch row
    instnorm_kernel<<<BATCH, 256>>>(x);

    // K3: qkv GEMM [32768,32]@[32,768]
    qkv_gemm_kernel<<<dim3(QKV_N / 64, ROWS / 64), 256>>>();

    // K4: causal flash attention
    attention_kernel<<<dim3(16, BATCH), 256, ATTN_SMEM>>>();

    // K5: fused head projection + MSE
    pred_loss_kernel<<<256, 256>>>();

    // K6: scalar out
    finalize_kernel<<<1, 1>>>(out);
}